// round 7
// baseline (speedup 1.0000x reference)
#include <cuda_runtime.h>
#include <cstdint>

#define NREL 500
#define NB   4096
#define DIM  256
#define CHUNK 16
#define E2S  260          // padded per-sample stride in u64 (4 pad u64)
#define KHO  65           // kh block offset in u64 (64 + 1 pad)

typedef unsigned long long ull;

// ---------------- device scratch ----------------
__device__ int g_offsets[NREL + 1];
__device__ int g_bucket[NB];

// ---------------- fused preprocessing: one CTA does everything ----------------
// zero counts -> detect int32/int64 -> smem histogram -> smem scan -> scatter
__global__ void k_prep(const int* __restrict__ rel32) {
    __shared__ int s_cnt[512];
    __shared__ int s_cur[NREL];
    __shared__ int s_stride;
    int t = threadIdx.x;           // 512 threads

    if (t < 32) {
        // int64 ids < 500 => every odd int32 word is 0; int32 => odd words live.
        unsigned b = __ballot_sync(0xFFFFFFFFu, rel32[2 * t + 1] != 0);
        if (t == 0) s_stride = b ? 1 : 2;
    }
    s_cnt[t] = 0;
    __syncthreads();
    int stride = s_stride;

    // histogram (shared atomics)
    for (int i = t; i < NB; i += 512) {
        int r = rel32[i * stride];
        r = max(0, min(NREL - 1, r));
        atomicAdd(&s_cnt[r], 1);
    }
    __syncthreads();
    int c = s_cnt[t];
    // Hillis-Steele inclusive scan over 512
    int v = c;
    for (int off = 1; off < 512; off <<= 1) {
        int u = (t >= off) ? s_cnt[t - off] : 0;
        __syncthreads();
        v += u;
        s_cnt[t] = v;
        __syncthreads();
    }
    if (t < NREL) {
        g_offsets[t + 1] = v;
        s_cur[t] = v - c;          // exclusive start
    }
    if (t == 0) g_offsets[0] = 0;
    __syncthreads();

    // scatter
    for (int i = t; i < NB; i += 512) {
        int r = rel32[i * stride];
        r = max(0, min(NREL - 1, r));
        int p = atomicAdd(&s_cur[r], 1);
        g_bucket[p] = i;
    }
}

// ---------------- packed f32x2 helpers ----------------
__device__ __forceinline__ ull ffma2(ull a, ull b, ull c) {   // a*b + c
    ull r;
    asm("fma.rn.f32x2 %0, %1, %2, %3;" : "=l"(r) : "l"(a), "l"(b), "l"(c));
    return r;
}
__device__ __forceinline__ ull addf2(ull a, ull b) {
    float2 x, y;
    x = *reinterpret_cast<float2*>(&a);
    y = *reinterpret_cast<float2*>(&b);
    x.x += y.x; x.y += y.y;
    return *reinterpret_cast<ull*>(&x);
}

// ---------------- main compute ----------------
// CTA = (relation r, column-half h). Thread: c = t>>2 (u64 column pair within
// half), kh = t&3 (K-quarter, adjacent lanes -> shfl reduction).
template <int NS>
__device__ __forceinline__ void compute_half(const ull* __restrict__ Mp,   // M64 + h*64 + c
                                             const ull* __restrict__ e2,  // s_e2 + kh*KHO
                                             ull* __restrict__ out64,
                                             int jbase, int n, int kh, int lane,
                                             int c, int h) {
    ull acc[NS];
#pragma unroll
    for (int s = 0; s < NS; ++s) acc[s] = 0ull;

#pragma unroll 4
    for (int j = 0; j < 64; ++j) {
        ull m = Mp[(kh * 64 + j) * 128];          // LDG.64, coalesced 256B/warp
#pragma unroll
        for (int s = 0; s < NS; ++s)
            acc[s] = ffma2(e2[s * E2S + j], m, acc[s]);   // LDS.64 broadcast + FFMA2
    }

    // reduce over kh (lanes l, l+1, l+2, l+3 share c)
#pragma unroll
    for (int s = 0; s < NS; ++s) {
        acc[s] = addf2(acc[s], __shfl_down_sync(0xFFFFFFFFu, acc[s], 2));
        acc[s] = addf2(acc[s], __shfl_down_sync(0xFFFFFFFFu, acc[s], 1));
    }
    if (kh == 0) {
#pragma unroll
        for (int s = 0; s < NS; ++s)
            if (s < n)
                out64[(size_t)g_bucket[jbase + s] * 128 + h * 64 + c] = acc[s];
    }
}

__global__ void __launch_bounds__(256) k_main(const float* __restrict__ emb,
                                              const float* __restrict__ mats,
                                              float* __restrict__ out) {
    __shared__ ull s_e2[CHUNK * E2S];   // duplicated embeddings, ~33 KB

    int r = blockIdx.x >> 1;
    int h = blockIdx.x & 1;
    int begin = g_offsets[r];
    int end   = g_offsets[r + 1];
    if (begin == end) return;

    const ull* M64 = reinterpret_cast<const ull*>(mats) + (size_t)r * (DIM * DIM / 2);
    ull* out64 = reinterpret_cast<ull*>(out);

    int t = threadIdx.x;
    int c = t >> 2;
    int kh = t & 3;
    int lane = t & 31;
    const ull* Mp = M64 + h * 64 + c;
    const ull* e2 = s_e2 + kh * KHO;

    for (int base = begin; base < end; base += CHUNK) {
        int n = min(CHUNK, end - base);
        int nsr = (n + 3) & ~3;

        // stage nsr embeddings, duplicated {v,v}, kh-padded layout
        for (int i = t; i < nsr * DIM; i += 256) {
            int s = i >> 8;
            int d = i & 255;
            float v = 0.0f;
            if (s < n) v = emb[(size_t)g_bucket[base + s] * DIM + d];
            float2 dd; dd.x = v; dd.y = v;
            s_e2[s * E2S + (d >> 6) * KHO + (d & 63)] = *reinterpret_cast<ull*>(&dd);
        }
        __syncthreads();

        switch (nsr) {
            case 4:  compute_half<4 >(Mp, e2, out64, base, n, kh, lane, c, h); break;
            case 8:  compute_half<8 >(Mp, e2, out64, base, n, kh, lane, c, h); break;
            case 12: compute_half<12>(Mp, e2, out64, base, n, kh, lane, c, h); break;
            default: compute_half<16>(Mp, e2, out64, base, n, kh, lane, c, h); break;
        }
        __syncthreads();   // protect s_e2 before next stage
    }
}

// ---------------- launch ----------------
extern "C" void kernel_launch(void* const* d_in, const int* in_sizes, int n_in,
                              void* d_out, int out_size) {
    const float* emb = nullptr;
    const int* rel = nullptr;
    const float* mats = nullptr;

    for (int i = 0; i < n_in; ++i) {
        if (in_sizes[i] == NB)                     rel  = (const int*)d_in[i];
        else if (in_sizes[i] == NB * DIM)          emb  = (const float*)d_in[i];
        else if (in_sizes[i] == NREL * DIM * DIM)  mats = (const float*)d_in[i];
    }
    if (!emb  && n_in > 0) emb  = (const float*)d_in[0];
    if (!rel  && n_in > 1) rel  = (const int*)d_in[1];
    if (!mats && n_in > 2) mats = (const float*)d_in[2];

    float* out = (float*)d_out;

    k_prep<<<1, 512>>>(rel);
    k_main<<<NREL * 2, 256>>>(emb, mats, out);
}

// round 8
// speedup vs baseline: 1.2444x; 1.2444x over previous
#include <cuda_runtime.h>
#include <cstdint>

#define NREL 500
#define NB   4096
#define DIM  256
#define CHUNK 12
#define ESTR 260          // per-sample float stride: 4 kh blocks of 65 (64+1 pad)

typedef unsigned long long ull;

// ---------------- device scratch ----------------
__device__ int g_offsets[NREL + 1];
__device__ int g_bucket[NB];

// ---------------- fused preprocessing (1 CTA) ----------------
__global__ void k_prep(const int* __restrict__ rel32) {
    __shared__ int s_cnt[512];
    __shared__ int s_cur[NREL];
    __shared__ int s_stride;
    int t = threadIdx.x;           // 512 threads

    if (t < 32) {
        // int64 ids < 500 => every odd int32 word is 0; int32 => odd words live.
        unsigned b = __ballot_sync(0xFFFFFFFFu, rel32[2 * t + 1] != 0);
        if (t == 0) s_stride = b ? 1 : 2;
    }
    s_cnt[t] = 0;
    __syncthreads();
    int stride = s_stride;

    for (int i = t; i < NB; i += 512) {
        int r = rel32[i * stride];
        r = max(0, min(NREL - 1, r));
        atomicAdd(&s_cnt[r], 1);
    }
    __syncthreads();
    int c = s_cnt[t];
    int v = c;
    for (int off = 1; off < 512; off <<= 1) {
        int u = (t >= off) ? s_cnt[t - off] : 0;
        __syncthreads();
        v += u;
        s_cnt[t] = v;
        __syncthreads();
    }
    if (t < NREL) {
        g_offsets[t + 1] = v;
        s_cur[t] = v - c;
    }
    if (t == 0) g_offsets[0] = 0;
    __syncthreads();

    for (int i = t; i < NB; i += 512) {
        int r = rel32[i * stride];
        r = max(0, min(NREL - 1, r));
        int p = atomicAdd(&s_cur[r], 1);
        g_bucket[p] = i;
    }
}

// ---------------- packed f32x2 helpers ----------------
__device__ __forceinline__ ull ffma2(ull a, ull b, ull c) {   // a*b + c
    ull r;
    asm("fma.rn.f32x2 %0, %1, %2, %3;" : "=l"(r) : "l"(a), "l"(b), "l"(c));
    return r;
}
__device__ __forceinline__ ull dup2(float a) {                // {a, a}
    ull r;
    asm("mov.b64 %0, {%1, %1};" : "=l"(r) : "f"(a));
    return r;
}
__device__ __forceinline__ ull addf2(ull a, ull b) {
    float2 x = *reinterpret_cast<float2*>(&a);
    float2 y = *reinterpret_cast<float2*>(&b);
    x.x += y.x; x.y += y.y;
    return *reinterpret_cast<ull*>(&x);
}

// ---------------- main compute ----------------
// CTA = relation. Thread: cg = t>>2 owns 2 adjacent u64 cols (16B, LDG.128),
// kh = t&3 owns a K-quarter (adjacent lanes -> shfl-4 reduce).
template <int NS>
__device__ __forceinline__ void compute(const ulonglong2* __restrict__ Mp, // pre-offset kh,cg
                                        const float* __restrict__ se,      // s_e + kh*65
                                        ull* __restrict__ out64,
                                        int jbase, int n, int kh, int cg) {
    ull a0[NS], a1[NS];
#pragma unroll
    for (int s = 0; s < NS; ++s) { a0[s] = 0ull; a1[s] = 0ull; }

#pragma unroll 4
    for (int j = 0; j < 64; ++j) {
        ulonglong2 m = Mp[j * 64];           // LDG.128: 4x128B contiguous per warp
#pragma unroll
        for (int s = 0; s < NS; ++s) {
            ull e = dup2(se[s * ESTR + j]);  // LDS.32 broadcast + ALU dup
            a0[s] = ffma2(e, m.x, a0[s]);
            a1[s] = ffma2(e, m.y, a1[s]);
        }
    }

    // reduce over kh (lanes l..l+3 share cg; only kh==0 lane's result is used)
#pragma unroll
    for (int s = 0; s < NS; ++s) {
        a0[s] = addf2(a0[s], __shfl_down_sync(0xFFFFFFFFu, a0[s], 2));
        a1[s] = addf2(a1[s], __shfl_down_sync(0xFFFFFFFFu, a1[s], 2));
        a0[s] = addf2(a0[s], __shfl_down_sync(0xFFFFFFFFu, a0[s], 1));
        a1[s] = addf2(a1[s], __shfl_down_sync(0xFFFFFFFFu, a1[s], 1));
    }
    if (kh == 0) {
#pragma unroll
        for (int s = 0; s < NS; ++s)
            if (s < n) {
                ulonglong2 o; o.x = a0[s]; o.y = a1[s];
                *reinterpret_cast<ulonglong2*>(
                    out64 + (size_t)g_bucket[jbase + s] * 128 + cg * 2) = o;  // STG.128
            }
    }
}

__global__ void __launch_bounds__(256) k_main(const float* __restrict__ emb,
                                              const float* __restrict__ mats,
                                              float* __restrict__ out) {
    __shared__ float s_e[CHUNK * ESTR];   // plain floats, kh-padded (12.5 KB)

    int r = blockIdx.x;
    int begin = g_offsets[r];
    int end   = g_offsets[r + 1];
    if (begin == end) return;

    int t = threadIdx.x;
    int cg = t >> 2;          // 64 column groups x 2 u64 = 128 u64 cols
    int kh = t & 3;           // K-quarter

    const ulonglong2* M2 = reinterpret_cast<const ulonglong2*>(mats) +
                           (size_t)r * (DIM * DIM / 4);
    const ulonglong2* Mp = M2 + kh * 64 * 64 + cg;
    const float* se = s_e + kh * 65;
    ull* out64 = reinterpret_cast<ull*>(out);

    for (int base = begin; base < end; base += CHUNK) {
        int n = min(CHUNK, end - base);
        int nsr = (n + 3) & ~3;

        // stage embeddings (zero-pad), layout: s*260 + (d>>6)*65 + (d&63)
        for (int i = t; i < nsr * DIM; i += 256) {
            int s = i >> 8;
            int d = i & 255;
            float v = 0.0f;
            if (s < n) v = emb[(size_t)g_bucket[base + s] * DIM + d];
            s_e[s * ESTR + (d >> 6) * 65 + (d & 63)] = v;
        }
        __syncthreads();

        switch (nsr) {
            case 4:  compute<4 >(Mp, se, out64, base, n, kh, cg); break;
            case 8:  compute<8 >(Mp, se, out64, base, n, kh, cg); break;
            default: compute<12>(Mp, se, out64, base, n, kh, cg); break;
        }
        __syncthreads();
    }
}

// ---------------- launch ----------------
extern "C" void kernel_launch(void* const* d_in, const int* in_sizes, int n_in,
                              void* d_out, int out_size) {
    const float* emb = nullptr;
    const int* rel = nullptr;
    const float* mats = nullptr;

    for (int i = 0; i < n_in; ++i) {
        if (in_sizes[i] == NB)                     rel  = (const int*)d_in[i];
        else if (in_sizes[i] == NB * DIM)          emb  = (const float*)d_in[i];
        else if (in_sizes[i] == NREL * DIM * DIM)  mats = (const float*)d_in[i];
    }
    if (!emb  && n_in > 0) emb  = (const float*)d_in[0];
    if (!rel  && n_in > 1) rel  = (const int*)d_in[1];
    if (!mats && n_in > 2) mats = (const float*)d_in[2];

    float* out = (float*)d_out;

    k_prep<<<1, 512>>>(rel);
    k_main<<<NREL, 256>>>(emb, mats, out);
}

// round 9
// speedup vs baseline: 1.4689x; 1.1803x over previous
#include <cuda_runtime.h>
#include <cstdint>

#define NREL 500
#define NB   4096
#define DIM  256
#define CHUNK 12
#define ESTR 260            // per-sample float stride in s_e
#define ROWB 528            // smem bytes per half-row (512 data + 16 pad: conflict-free LDS.128)
#define TROWS 16            // rows per pipeline tile
#define BUFB (TROWS * ROWB) // 8448 B per stage
#define NSTAGE 4

typedef unsigned long long ull;

// ---------------- device scratch ----------------
__device__ int g_offsets[NREL + 1];
__device__ int g_bucket[NB];

// ---------------- fused preprocessing (1 CTA) ----------------
__global__ void k_prep(const int* __restrict__ rel32) {
    __shared__ int s_cnt[512];
    __shared__ int s_cur[NREL];
    __shared__ int s_stride;
    int t = threadIdx.x;           // 512 threads

    if (t < 32) {
        unsigned b = __ballot_sync(0xFFFFFFFFu, rel32[2 * t + 1] != 0);
        if (t == 0) s_stride = b ? 1 : 2;   // int64 ids => odd words all zero
    }
    s_cnt[t] = 0;
    __syncthreads();
    int stride = s_stride;

    for (int i = t; i < NB; i += 512) {
        int r = rel32[i * stride];
        r = max(0, min(NREL - 1, r));
        atomicAdd(&s_cnt[r], 1);
    }
    __syncthreads();
    int c = s_cnt[t];
    int v = c;
    for (int off = 1; off < 512; off <<= 1) {
        int u = (t >= off) ? s_cnt[t - off] : 0;
        __syncthreads();
        v += u;
        s_cnt[t] = v;
        __syncthreads();
    }
    if (t < NREL) {
        g_offsets[t + 1] = v;
        s_cur[t] = v - c;
    }
    if (t == 0) g_offsets[0] = 0;
    __syncthreads();

    for (int i = t; i < NB; i += 512) {
        int r = rel32[i * stride];
        r = max(0, min(NREL - 1, r));
        int p = atomicAdd(&s_cur[r], 1);
        g_bucket[p] = i;
    }
}

// ---------------- helpers ----------------
__device__ __forceinline__ ull ffma2(ull a, ull b, ull c) {
    ull r;
    asm("fma.rn.f32x2 %0, %1, %2, %3;" : "=l"(r) : "l"(a), "l"(b), "l"(c));
    return r;
}
__device__ __forceinline__ ull dup2(float a) {
    ull r;
    asm("mov.b64 %0, {%1, %1};" : "=l"(r) : "f"(a));
    return r;
}
__device__ __forceinline__ ull addf2(ull a, ull b) {
    float2 x = *reinterpret_cast<float2*>(&a);
    float2 y = *reinterpret_cast<float2*>(&b);
    x.x += y.x; x.y += y.y;
    return *reinterpret_cast<ull*>(&x);
}
__device__ __forceinline__ uint32_t smem_u32(const void* p) {
    return (uint32_t)__cvta_generic_to_shared(p);
}
__device__ __forceinline__ void cp16(uint32_t dst, const void* src) {
    asm volatile("cp.async.cg.shared.global [%0], [%1], 16;" :: "r"(dst), "l"(src));
}
__device__ __forceinline__ void cp_commit() { asm volatile("cp.async.commit_group;"); }
template <int N>
__device__ __forceinline__ void cp_wait() { asm volatile("cp.async.wait_group %0;" :: "n"(N)); }

// stage one 16-row half-matrix tile into SMEM ring (512 granules of 16B, 2/thread)
__device__ __forceinline__ void issue_tile(const char* gM, uint32_t smbase, int tile, int t) {
    uint32_t dst = smbase + (uint32_t)(tile & 3) * BUFB;
#pragma unroll
    for (int g = t; g < 512; g += 256) {
        int row = g >> 5, c = g & 31;
        cp16(dst + row * ROWB + c * 16,
             gM + (size_t)(tile * TROWS + row) * 1024 + c * 16);
    }
}

// one tile of compute: 2 subrows per thread (row = i*16 + sr*8 + kh)
template <int NS>
__device__ __forceinline__ void compute_tile(const char* buf, int i, const float* se,
                                             int kh, int cg, ull* a0, ull* a1) {
#pragma unroll
    for (int sr = 0; sr < 2; ++sr) {
        int rl = sr * 8 + kh;
        ulonglong2 m = *reinterpret_cast<const ulonglong2*>(buf + rl * ROWB + cg * 16);
        int d = i * TROWS + rl;
#pragma unroll
        for (int s = 0; s < NS; ++s) {
            ull e = dup2(se[s * ESTR + d]);       // LDS.32 + ALU dup
            a0[s] = ffma2(e, m.x, a0[s]);
            a1[s] = ffma2(e, m.y, a1[s]);
        }
    }
}

template <int NS>
__device__ __forceinline__ void run_chunk(const char* gM, char* s_m, const float* se,
                                          ull* out64, int jbase, int n,
                                          int t, int kh, int cg, int h) {
    uint32_t smbase = smem_u32(s_m);
    issue_tile(gM, smbase, 0, t); cp_commit();
    issue_tile(gM, smbase, 1, t); cp_commit();
    issue_tile(gM, smbase, 2, t); cp_commit();

    ull a0[NS], a1[NS];
#pragma unroll
    for (int s = 0; s < NS; ++s) { a0[s] = 0ull; a1[s] = 0ull; }

    // main: tiles 0..13 (group g holds tile g; wait<2> => tile i landed)
    for (int i = 0; i < 14; ++i) {
        cp_wait<2>();
        __syncthreads();                       // other threads' copies + buffer reuse
        if (i < 13) { issue_tile(gM, smbase, i + 3, t); cp_commit(); }
        compute_tile<NS>(s_m + (i & 3) * BUFB, i, se, kh, cg, a0, a1);
    }
    cp_wait<1>(); __syncthreads();
    compute_tile<NS>(s_m + (14 & 3) * BUFB, 14, se, kh, cg, a0, a1);
    cp_wait<0>(); __syncthreads();
    compute_tile<NS>(s_m + (15 & 3) * BUFB, 15, se, kh, cg, a0, a1);

    // reduce over kh (8-lane groups share cg)
#pragma unroll
    for (int s = 0; s < NS; ++s) {
        a0[s] = addf2(a0[s], __shfl_down_sync(0xFFFFFFFFu, a0[s], 4));
        a1[s] = addf2(a1[s], __shfl_down_sync(0xFFFFFFFFu, a1[s], 4));
        a0[s] = addf2(a0[s], __shfl_down_sync(0xFFFFFFFFu, a0[s], 2));
        a1[s] = addf2(a1[s], __shfl_down_sync(0xFFFFFFFFu, a1[s], 2));
        a0[s] = addf2(a0[s], __shfl_down_sync(0xFFFFFFFFu, a0[s], 1));
        a1[s] = addf2(a1[s], __shfl_down_sync(0xFFFFFFFFu, a1[s], 1));
    }
    if (kh == 0) {
#pragma unroll
        for (int s = 0; s < NS; ++s)
            if (s < n) {
                ulonglong2 o; o.x = a0[s]; o.y = a1[s];
                *reinterpret_cast<ulonglong2*>(
                    out64 + (size_t)g_bucket[jbase + s] * 128 + h * 64 + cg * 2) = o;
            }
    }
}

// ---------------- main: CTA = (relation, column-half) ----------------
__global__ void __launch_bounds__(256) k_main(const float* __restrict__ emb,
                                              const float* __restrict__ mats,
                                              float* __restrict__ out) {
    __shared__ float s_e[CHUNK * ESTR];                 // 12480 B
    __shared__ __align__(16) char s_m[NSTAGE * BUFB];   // 33792 B

    int r = blockIdx.x >> 1;
    int h = blockIdx.x & 1;
    int begin = g_offsets[r];
    int end   = g_offsets[r + 1];
    if (begin == end) return;

    int t  = threadIdx.x;
    int kh = t & 7;           // row class (mod 8)
    int cg = t >> 3;          // 0..31: owns u64 cols h*64 + 2cg, 2cg+1

    const char* gM = reinterpret_cast<const char*>(mats) +
                     (size_t)r * (DIM * DIM * 4) + (size_t)h * 512;   // half offset
    ull* out64 = reinterpret_cast<ull*>(out);

    for (int base = begin; base < end; base += CHUNK) {
        int n = min(CHUNK, end - base);
        int nsr = (n + 3) & ~3;

        for (int i = t; i < nsr * DIM; i += 256) {
            int s = i >> 8;
            int d = i & 255;
            float v = 0.0f;
            if (s < n) v = emb[(size_t)g_bucket[base + s] * DIM + d];
            s_e[s * ESTR + d] = v;
        }
        __syncthreads();

        switch (nsr) {
            case 4:  run_chunk<4 >(gM, s_m, s_e, out64, base, n, t, kh, cg, h); break;
            case 8:  run_chunk<8 >(gM, s_m, s_e, out64, base, n, t, kh, cg, h); break;
            default: run_chunk<12>(gM, s_m, s_e, out64, base, n, t, kh, cg, h); break;
        }
        __syncthreads();
    }
}

// ---------------- launch ----------------
extern "C" void kernel_launch(void* const* d_in, const int* in_sizes, int n_in,
                              void* d_out, int out_size) {
    const float* emb = nullptr;
    const int* rel = nullptr;
    const float* mats = nullptr;

    for (int i = 0; i < n_in; ++i) {
        if (in_sizes[i] == NB)                     rel  = (const int*)d_in[i];
        else if (in_sizes[i] == NB * DIM)          emb  = (const float*)d_in[i];
        else if (in_sizes[i] == NREL * DIM * DIM)  mats = (const float*)d_in[i];
    }
    if (!emb  && n_in > 0) emb  = (const float*)d_in[0];
    if (!rel  && n_in > 1) rel  = (const int*)d_in[1];
    if (!mats && n_in > 2) mats = (const float*)d_in[2];

    float* out = (float*)d_out;

    k_prep<<<1, 512>>>(rel);
    k_main<<<NREL * 2, 256>>>(emb, mats, out);
}

// round 10
// speedup vs baseline: 1.6800x; 1.1438x over previous
#include <cuda_runtime.h>
#include <cstdint>

#define NREL 500
#define NB   4096
#define DIM  256
#define CHUNK 12
#define ESTR 260            // per-sample float stride in s_e
#define ROWB 528            // smem bytes per half-row (512 data + 16 pad)
#define TROWS 16            // rows per pipeline tile
#define BUFB (TROWS * ROWB) // 8448 B per stage
#define NSTAGE 4

typedef unsigned long long ull;

// ---------------- device scratch ----------------
__device__ int g_offsets[NREL + 1];
__device__ int g_bucket[NB];
__device__ int g_order[NREL];     // relations sorted by bucket size, descending

// ---------------- fused preprocessing (1 CTA) ----------------
__global__ void k_prep(const int* __restrict__ rel32) {
    __shared__ int s_cnt[512];
    __shared__ int s_cur[NREL];
    __shared__ int s_chist[64];
    __shared__ int s_ccur[64];
    __shared__ int s_stride;
    int t = threadIdx.x;           // 512 threads

    if (t < 32) {
        unsigned b = __ballot_sync(0xFFFFFFFFu, rel32[2 * t + 1] != 0);
        if (t == 0) s_stride = b ? 1 : 2;   // int64 ids => odd words all zero
    }
    s_cnt[t] = 0;
    if (t < 64) s_chist[t] = 0;
    __syncthreads();
    int stride = s_stride;

    for (int i = t; i < NB; i += 512) {
        int r = rel32[i * stride];
        r = max(0, min(NREL - 1, r));
        atomicAdd(&s_cnt[r], 1);
    }
    __syncthreads();
    int c = s_cnt[t];
    int v = c;
    for (int off = 1; off < 512; off <<= 1) {
        int u = (t >= off) ? s_cnt[t - off] : 0;
        __syncthreads();
        v += u;
        s_cnt[t] = v;
        __syncthreads();
    }
    if (t < NREL) {
        g_offsets[t + 1] = v;
        s_cur[t] = v - c;
        atomicAdd(&s_chist[min(c, 63)], 1);   // histogram of bucket sizes
    }
    if (t == 0) g_offsets[0] = 0;
    __syncthreads();

    // descending-count offsets (serial over 64 bins, thread 0)
    if (t == 0) {
        int acc = 0;
        for (int k = 63; k >= 0; --k) { s_ccur[k] = acc; acc += s_chist[k]; }
    }
    __syncthreads();
    if (t < NREL) {
        int p = atomicAdd(&s_ccur[min(c, 63)], 1);
        g_order[p] = t;
    }

    for (int i = t; i < NB; i += 512) {
        int r = rel32[i * stride];
        r = max(0, min(NREL - 1, r));
        int p = atomicAdd(&s_cur[r], 1);
        g_bucket[p] = i;
    }
}

// ---------------- helpers ----------------
__device__ __forceinline__ ull ffma2(ull a, ull b, ull c) {
    ull r;
    asm("fma.rn.f32x2 %0, %1, %2, %3;" : "=l"(r) : "l"(a), "l"(b), "l"(c));
    return r;
}
__device__ __forceinline__ ull dup2(float a) {
    ull r;
    asm("mov.b64 %0, {%1, %1};" : "=l"(r) : "f"(a));
    return r;
}
__device__ __forceinline__ ull addf2(ull a, ull b) {
    float2 x = *reinterpret_cast<float2*>(&a);
    float2 y = *reinterpret_cast<float2*>(&b);
    x.x += y.x; x.y += y.y;
    return *reinterpret_cast<ull*>(&x);
}
__device__ __forceinline__ uint32_t smem_u32(const void* p) {
    return (uint32_t)__cvta_generic_to_shared(p);
}
__device__ __forceinline__ void cp16(uint32_t dst, const void* src) {
    asm volatile("cp.async.cg.shared.global [%0], [%1], 16;" :: "r"(dst), "l"(src));
}
__device__ __forceinline__ void cp_commit() { asm volatile("cp.async.commit_group;"); }
template <int N>
__device__ __forceinline__ void cp_wait() { asm volatile("cp.async.wait_group %0;" :: "n"(N)); }

// stage one 16-row half-matrix tile into SMEM ring (512 granules of 16B, 2/thread)
__device__ __forceinline__ void issue_tile(const char* gM, uint32_t smbase, int tile, int t) {
#pragma unroll
    for (int g = t; g < 512; g += 256) {
        int row = g >> 5, c = g & 31;
        cp16(smbase + (uint32_t)(tile & 3) * BUFB + row * ROWB + c * 16,
             gM + (size_t)(tile * TROWS + row) * 1024 + c * 16);
    }
}

// one tile of compute: 2 subrows per thread (row = i*16 + sr*8 + kh)
template <int NS>
__device__ __forceinline__ void compute_tile(const char* buf, int i, const float* se,
                                             int kh, int cg, ull* a0, ull* a1) {
#pragma unroll
    for (int sr = 0; sr < 2; ++sr) {
        int rl = sr * 8 + kh;
        ulonglong2 m = *reinterpret_cast<const ulonglong2*>(buf + rl * ROWB + cg * 16);
        int d = i * TROWS + rl;
#pragma unroll
        for (int s = 0; s < NS; ++s) {
            ull e = dup2(se[s * ESTR + d]);       // LDS.32 + ALU dup
            a0[s] = ffma2(e, m.x, a0[s]);
            a1[s] = ffma2(e, m.y, a1[s]);
        }
    }
}

template <int NS>
__device__ __forceinline__ void run_chunk(const char* gM, char* s_m, const float* se,
                                          ull* out64, int jbase, int n,
                                          int t, int kh, int cg, int h) {
    uint32_t smbase = smem_u32(s_m);
    issue_tile(gM, smbase, 0, t); cp_commit();
    issue_tile(gM, smbase, 1, t); cp_commit();
    issue_tile(gM, smbase, 2, t); cp_commit();

    ull a0[NS], a1[NS];
#pragma unroll
    for (int s = 0; s < NS; ++s) { a0[s] = 0ull; a1[s] = 0ull; }

    for (int i = 0; i < 14; ++i) {
        cp_wait<2>();
        __syncthreads();
        if (i < 13) { issue_tile(gM, smbase, i + 3, t); cp_commit(); }
        compute_tile<NS>(s_m + (i & 3) * BUFB, i, se, kh, cg, a0, a1);
    }
    cp_wait<1>(); __syncthreads();
    compute_tile<NS>(s_m + (14 & 3) * BUFB, 14, se, kh, cg, a0, a1);
    cp_wait<0>(); __syncthreads();
    compute_tile<NS>(s_m + (15 & 3) * BUFB, 15, se, kh, cg, a0, a1);

    // reduce over kh (8-lane groups share cg)
#pragma unroll
    for (int s = 0; s < NS; ++s) {
        a0[s] = addf2(a0[s], __shfl_down_sync(0xFFFFFFFFu, a0[s], 4));
        a1[s] = addf2(a1[s], __shfl_down_sync(0xFFFFFFFFu, a1[s], 4));
        a0[s] = addf2(a0[s], __shfl_down_sync(0xFFFFFFFFu, a0[s], 2));
        a1[s] = addf2(a1[s], __shfl_down_sync(0xFFFFFFFFu, a1[s], 2));
        a0[s] = addf2(a0[s], __shfl_down_sync(0xFFFFFFFFu, a0[s], 1));
        a1[s] = addf2(a1[s], __shfl_down_sync(0xFFFFFFFFu, a1[s], 1));
    }
    if (kh == 0) {
#pragma unroll
        for (int s = 0; s < NS; ++s)
            if (s < n) {
                ulonglong2 o; o.x = a0[s]; o.y = a1[s];
                *reinterpret_cast<ulonglong2*>(
                    out64 + (size_t)g_bucket[jbase + s] * 128 + h * 64 + cg * 2) = o;
            }
    }
}

// ---------------- main: CTA = (relation, column-half), 3 CTAs/SM ----------------
__global__ void __launch_bounds__(256, 3) k_main(const float* __restrict__ emb,
                                                 const float* __restrict__ mats,
                                                 float* __restrict__ out) {
    __shared__ float s_e[CHUNK * ESTR];                 // 12480 B
    __shared__ __align__(16) char s_m[NSTAGE * BUFB];   // 33792 B

    int r = g_order[blockIdx.x >> 1];     // big buckets first
    int h = blockIdx.x & 1;
    int begin = g_offsets[r];
    int end   = g_offsets[r + 1];
    if (begin == end) return;

    int t  = threadIdx.x;
    int kh = t & 7;           // row class (mod 8)
    int cg = t >> 3;          // 0..31: owns u64 cols h*64 + 2cg, 2cg+1

    const char* gM = reinterpret_cast<const char*>(mats) +
                     (size_t)r * (DIM * DIM * 4) + (size_t)h * 512;   // half offset
    ull* out64 = reinterpret_cast<ull*>(out);

    for (int base = begin; base < end; base += CHUNK) {
        int n = min(CHUNK, end - base);
        int nsr = (n + 3) & ~3;

        for (int i = t; i < nsr * DIM; i += 256) {
            int s = i >> 8;
            int d = i & 255;
            float v = 0.0f;
            if (s < n) v = emb[(size_t)g_bucket[base + s] * DIM + d];
            s_e[s * ESTR + d] = v;
        }
        __syncthreads();

        switch (nsr) {
            case 4:  run_chunk<4 >(gM, s_m, s_e, out64, base, n, t, kh, cg, h); break;
            case 8:  run_chunk<8 >(gM, s_m, s_e, out64, base, n, t, kh, cg, h); break;
            default: run_chunk<12>(gM, s_m, s_e, out64, base, n, t, kh, cg, h); break;
        }
        __syncthreads();
    }
}

// ---------------- launch ----------------
extern "C" void kernel_launch(void* const* d_in, const int* in_sizes, int n_in,
                              void* d_out, int out_size) {
    const float* emb = nullptr;
    const int* rel = nullptr;
    const float* mats = nullptr;

    for (int i = 0; i < n_in; ++i) {
        if (in_sizes[i] == NB)                     rel  = (const int*)d_in[i];
        else if (in_sizes[i] == NB * DIM)          emb  = (const float*)d_in[i];
        else if (in_sizes[i] == NREL * DIM * DIM)  mats = (const float*)d_in[i];
    }
    if (!emb  && n_in > 0) emb  = (const float*)d_in[0];
    if (!rel  && n_in > 1) rel  = (const int*)d_in[1];
    if (!mats && n_in > 2) mats = (const float*)d_in[2];

    float* out = (float*)d_out;

    k_prep<<<1, 512>>>(rel);
    k_main<<<NREL * 2, 256>>>(emb, mats, out);
}